// round 15
// baseline (speedup 1.0000x reference)
#include <cuda_runtime.h>
#include <math.h>

typedef unsigned long long ull;
typedef unsigned int uint;

#define N_B 8
#define C_IN 64
#define C_H 32
#define HI 384
#define WI 384
#define HO 192
#define WO 192
#define HWI (HI*WI)
#define HWO (HO*WO)
#define NPIX_CH (N_B*HWO)

// ---------------- scratch ----------------
__device__ float g_mean[N_B*C_IN];
__device__ float g_att[2*N_B*4];
__device__ float g_sqw[C_IN*9*128];                      // [ci][k9][co*2 dup]
__device__ float g_wv[N_B*C_H*3*64];
__device__ float g_wh[N_B*C_H*3*64];
__device__ float g_ev [(size_t)N_B*C_IN*HI*192];         // Ev[k]  = x[2k]
__device__ float g_od [(size_t)N_B*C_IN*HI*192];         // Od[k]  = x[2k+1]
__device__ float g_ods[(size_t)N_B*C_IN*HI*192];         // OdS[k] = x[2k-1], OdS[0]=0
__device__ float g_vraw[(size_t)N_B*C_H*HWO];
__device__ float g_hraw[(size_t)N_B*C_H*HWO];
__device__ float g_stats[2*C_H*2];

// ---------------- helpers ----------------
__device__ __forceinline__ void unpack2(ull v, float& a, float& b) {
    asm("mov.b64 {%0, %1}, %2;" : "=f"(a), "=f"(b) : "l"(v));
}
__device__ __forceinline__ void ffma2(ull& d, ull a, ull b) {
    asm("fma.rn.f32x2 %0, %1, %2, %0;" : "+l"(d) : "l"(a), "l"(b));
}
__device__ __forceinline__ uint smem_u32(const void* p) {
    uint a; asm("{ .reg .u64 t; cvta.to.shared.u64 t, %1; cvt.u32.u64 %0, t; }" : "=r"(a) : "l"(p));
    return a;
}
__device__ __forceinline__ void cp16(uint dst, const void* src) {
    asm volatile("{ .reg .u64 g; cvta.to.global.u64 g, %1;"
                 " cp.async.cg.shared.global [%0], [g], 16; }"
                 :: "r"(dst), "l"(src) : "memory");
}
__device__ __forceinline__ void cp16z(uint dst, const void* src, uint sz) {
    asm volatile("{ .reg .u64 g; cvta.to.global.u64 g, %1;"
                 " cp.async.cg.shared.global [%0], [g], 16, %2; }"
                 :: "r"(dst), "l"(src), "r"(sz) : "memory");
}
#define CP_COMMIT() asm volatile("cp.async.commit_group;" ::: "memory")
#define CP_WAIT(n)  asm volatile("cp.async.wait_group %0;" :: "n"(n) : "memory")

// ---------------- 1) global deinterleave + channel sums (no shfl chain) ----------------
__global__ void __launch_bounds__(256)
deint_kernel(const float* __restrict__ x) {
    int nc = blockIdx.x;
    const float* src = x + (size_t)nc * HWI;
    float* ev  = g_ev  + (size_t)nc * HI * 192;
    float* od  = g_od  + (size_t)nc * HI * 192;
    float* ods = g_ods + (size_t)nc * HI * 192;
    const int lane = threadIdx.x & 31, wid = threadIdx.x >> 5;
    float s = 0.f;

    for (int row = wid; row < HI; row += 8) {
        const float* r = src + (size_t)row * WI;
        float* evr  = ev  + row * 192;
        float* odr  = od  + row * 192;
        float* odsr = ods + row * 192;
        #pragma unroll
        for (int it = 0; it < 2; it++) {
            int g = it * 32 + lane;
            if (g < 48) {
                float4 a = *(const float4*)(r + 8 * g);
                float4 b = *(const float4*)(r + 8 * g + 4);
                float prev = (g > 0) ? r[8 * g - 1] : 0.f;   // direct re-read (L1 hit)
                *(float4*)(evr  + 4*g) = make_float4(a.x, a.z, b.x, b.z);
                *(float4*)(odr  + 4*g) = make_float4(a.y, a.w, b.y, b.w);
                *(float4*)(odsr + 4*g) = make_float4(prev, a.y, a.w, b.y);
                s += a.x + a.y + a.z + a.w + b.x + b.y + b.z + b.w;
            }
        }
    }
    __shared__ float red[256];
    red[threadIdx.x] = s; __syncthreads();
    for (int o = 128; o > 0; o >>= 1) {
        if (threadIdx.x < o) red[threadIdx.x] += red[threadIdx.x + o];
        __syncthreads();
    }
    if (threadIdx.x == 0) g_mean[nc] = red[0];
}

// ---------------- 2a) sq weight transpose (independent of x / attention) ----------------
__global__ void sqprep_kernel(const float* __restrict__ sq_w) {
    int idx = blockIdx.x * 256 + threadIdx.x;      // 144 blocks
    if (idx < C_IN*9*64) {
        int co = idx & 63, k = (idx >> 6) % 9, ci = idx / 576;
        float w = sq_w[(co * C_IN + ci) * 9 + k];
        int o = (ci * 9 + k) * 128 + co * 2;
        g_sqw[o] = w; g_sqw[o + 1] = w;
    }
}

// ---------------- 2b) attention + zero stats (side stream) ----------------
__global__ void att_kernel(const float* __restrict__ aw_v, const float* __restrict__ ab_v,
                           const float* __restrict__ aw_h, const float* __restrict__ ab_h) {
    int t = threadIdx.x;
    if (t < 64) {
        int dir = t >> 5, n = (t >> 2) & 7, k = t & 3;
        const float* aw = dir ? aw_h : aw_v;
        const float* ab = dir ? ab_h : ab_v;
        const float* m = g_mean + n * C_IN + dir * C_H;
        float s = 0.f;
        #pragma unroll
        for (int ci = 0; ci < C_H; ci++) s += m[ci] * aw[k * C_H + ci];
        s = s * (1.f / (float)HWI) + ab[k];
        g_att[t] = 1.f / (1.f + expf(-s));
    }
    if (t < 128) g_stats[t] = 0.f;
}

// ---------------- 2c) v/h expert aggregation (side stream) ----------------
__global__ void vhprep_kernel(const float* __restrict__ w_v, const float* __restrict__ w_h) {
    int r = blockIdx.x * 256 + threadIdx.x;        // 192 blocks, 49152 items
    if (r < 2*24576) {
        int dir = r / 24576; r %= 24576;
        int co = r & 31, kh = (r >> 5) % 3, ci = (r / 96) & 31, n = r / 3072;
        const float* w = dir ? w_h : w_v;
        const float* att = &g_att[dir * 32 + n * 4];
        float v = 0.f;
        #pragma unroll
        for (int k = 0; k < 4; k++) v += att[k] * w[((k * 32 + co) * 32 + ci) * 3 + kh];
        float* dst = dir ? g_wh : g_wv;
        int o = ((n * 32 + ci) * 3 + kh) * 64 + co * 2;
        dst[o] = v; dst[o + 1] = v;
    }
}

// ---------------- 4) square 3x3 s2 conv — big tile + row reuse ----------------
#define SQ_W_OFF   9216
#define SQ_ST      13824
#define SQ_SMEM_BYTES (2*SQ_ST*4)

__global__ void __launch_bounds__(256, 2)
sq_kernel(const float* __restrict__ x, const float* __restrict__ sq_b, float* __restrict__ out) {
    extern __shared__ float sm[];
    const int tid = threadIdx.x;
    const int tx = tid & 15, ty = (tid >> 4) & 1, tc = tid >> 5;
    const int lane = tid & 31, wid = tid >> 5;
    const int x0 = blockIdx.x * 64, y0 = blockIdx.y * 4, n = blockIdx.z;
    const int gy0 = 2*y0 - 1;
    const uint sbase = smem_u32(sm);

    ull acc[2][2][8];
    #pragma unroll
    for (int a = 0; a < 2; a++)
        #pragma unroll
        for (int b = 0; b < 2; b++)
            #pragma unroll
            for (int j = 0; j < 8; j++) acc[a][b][j] = 0ULL;

    auto load_chunk = [&](int ci0, int stage) {
        uint st = sbase + (uint)stage * (SQ_ST * 4);
        for (int row = wid; row < 36; row += 8) {
            int ci = row / 9, r = row - ci * 9;
            int gy = gy0 + r;
            bool vy = (gy >= 0);
            size_t rb = ((size_t)(n * C_IN + ci0 + ci) * HI + (vy ? gy : 0)) * 192 + x0;
            uint so = st + (uint)row * 64 * 4;
            uint sz = vy ? 16u : 0u;
            #pragma unroll
            for (int i = lane; i < 48; i += 32) {
                int arr = i >> 4, g = i & 15;
                const float* gs = (arr == 0 ? g_ods : arr == 1 ? g_ev : g_od) + rb + g * 4;
                cp16z(so + (uint)arr * (2304 * 4) + g * 16, gs, sz);
            }
        }
        const float4* wsrc = (const float4*)(g_sqw + ci0 * 9 * 128);
        uint wb = st + SQ_W_OFF * 4;
        #pragma unroll
        for (int i = 0; i < 5; i++) {
            int k = tid + i * 256;
            if (k < 1152) cp16(wb + k * 16, wsrc + k);
        }
    };

    load_chunk(0, 0);
    CP_COMMIT();

    for (int ch = 0; ch < 16; ch++) {
        if (ch < 15) {
            load_chunk((ch + 1) * 4, (ch + 1) & 1);
            CP_COMMIT();
            CP_WAIT(1);
        } else {
            CP_WAIT(0);
        }
        __syncthreads();

        const float* base = sm + (ch & 1) * SQ_ST;
        const float* sW   = base + SQ_W_OFF;

        #pragma unroll
        for (int ci = 0; ci < 4; ci++) {
            ulonglong2 row2[3];
            #pragma unroll
            for (int kh = 0; kh < 3; kh++) {
                const int oA = ((ci * 9 + 4 * ty + kh)) * 64 + 4 * tx;
                const int oB = oA + 2 * 64;
                ulonglong2 inA[3], inB[3];
                if (kh == 2) {
                    inA[0] = row2[0]; inA[1] = row2[1]; inA[2] = row2[2];
                } else {
                    inA[0] = *(const ulonglong2*)&base[0*2304 + oA];
                    inA[1] = *(const ulonglong2*)&base[1*2304 + oA];
                    inA[2] = *(const ulonglong2*)&base[2*2304 + oA];
                }
                inB[0] = *(const ulonglong2*)&base[0*2304 + oB];
                inB[1] = *(const ulonglong2*)&base[1*2304 + oB];
                inB[2] = *(const ulonglong2*)&base[2*2304 + oB];
                if (kh == 0) {
                    row2[0] = inB[0]; row2[1] = inB[1]; row2[2] = inB[2];
                }
                #pragma unroll
                for (int kw = 0; kw < 3; kw++) {
                    const float* wp = &sW[(ci * 9 + kh * 3 + kw) * 128 + tc * 16];
                    ulonglong2 wA = *(const ulonglong2*)(wp);
                    ulonglong2 wB = *(const ulonglong2*)(wp + 4);
                    ulonglong2 wC = *(const ulonglong2*)(wp + 8);
                    ulonglong2 wD = *(const ulonglong2*)(wp + 12);
                    ffma2(acc[0][0][0], inA[kw].x, wA.x); ffma2(acc[0][0][1], inA[kw].x, wA.y);
                    ffma2(acc[0][0][2], inA[kw].x, wB.x); ffma2(acc[0][0][3], inA[kw].x, wB.y);
                    ffma2(acc[0][0][4], inA[kw].x, wC.x); ffma2(acc[0][0][5], inA[kw].x, wC.y);
                    ffma2(acc[0][0][6], inA[kw].x, wD.x); ffma2(acc[0][0][7], inA[kw].x, wD.y);
                    ffma2(acc[0][1][0], inA[kw].y, wA.x); ffma2(acc[0][1][1], inA[kw].y, wA.y);
                    ffma2(acc[0][1][2], inA[kw].y, wB.x); ffma2(acc[0][1][3], inA[kw].y, wB.y);
                    ffma2(acc[0][1][4], inA[kw].y, wC.x); ffma2(acc[0][1][5], inA[kw].y, wC.y);
                    ffma2(acc[0][1][6], inA[kw].y, wD.x); ffma2(acc[0][1][7], inA[kw].y, wD.y);
                    ffma2(acc[1][0][0], inB[kw].x, wA.x); ffma2(acc[1][0][1], inB[kw].x, wA.y);
                    ffma2(acc[1][0][2], inB[kw].x, wB.x); ffma2(acc[1][0][3], inB[kw].x, wB.y);
                    ffma2(acc[1][0][4], inB[kw].x, wC.x); ffma2(acc[1][0][5], inB[kw].x, wC.y);
                    ffma2(acc[1][0][6], inB[kw].x, wD.x); ffma2(acc[1][0][7], inB[kw].x, wD.y);
                    ffma2(acc[1][1][0], inB[kw].y, wA.x); ffma2(acc[1][1][1], inB[kw].y, wA.y);
                    ffma2(acc[1][1][2], inB[kw].y, wB.x); ffma2(acc[1][1][3], inB[kw].y, wB.y);
                    ffma2(acc[1][1][4], inB[kw].y, wC.x); ffma2(acc[1][1][5], inB[kw].y, wC.y);
                    ffma2(acc[1][1][6], inB[kw].y, wD.x); ffma2(acc[1][1][7], inB[kw].y, wD.y);
                }
            }
        }
        __syncthreads();
    }

    #pragma unroll
    for (int j = 0; j < 8; j++) {
        int co = tc * 8 + j;
        float bias = sq_b[co];
        int oc = ((co & 15) << 3) + (co >> 4);
        #pragma unroll
        for (int yy = 0; yy < 2; yy++) {
            int y = y0 + 2 * ty + yy;
            float4 o;
            unpack2(acc[yy][0][j], o.x, o.y);
            unpack2(acc[yy][1][j], o.z, o.w);
            o.x += bias; o.y += bias; o.z += bias; o.w += bias;
            *(float4*)&out[((size_t)(n * 128 + oc) * HO + y) * WO + x0 + 4 * tx] = o;
        }
    }
}

// ---------------- 5) vertical CondConv (3x1, s2) — widened ----------------
#define V_W_OFF  (32*9*64)
#define V_SMEM_BYTES ((32*9*64 + 32*3*64) * 4)
__global__ void __launch_bounds__(256)
v_kernel(const float* __restrict__ x) {
    extern __shared__ float sm[];
    float* s_in = sm;
    float* s_w  = sm + V_W_OFF;
    const int tid = threadIdx.x;
    const int tx = tid & 15, ty = (tid >> 4) & 3, tc = tid >> 6;
    const int x0 = blockIdx.x * 64, y0 = blockIdx.y * 4, n = blockIdx.z;
    const int gy0 = 2*y0 - 1;
    const uint sbase = smem_u32(sm);

    for (int i = tid; i < 4608; i += 256) {
        int row = i >> 4, g = i & 15;
        int ci = row / 9, r = row - ci * 9;
        int gy = gy0 + r;
        bool vy = (gy >= 0);
        const float* gs = g_ev + ((size_t)(n * C_IN + ci) * HI + (vy ? gy : 0)) * 192 + x0 + g * 4;
        cp16z(sbase + (uint)i * 16, gs, vy ? 16u : 0u);
    }
    {
        const float4* wsrc = (const float4*)(g_wv + (size_t)n * 32 * 192);
        uint wb = sbase + V_W_OFF * 4;
        #pragma unroll
        for (int i = 0; i < 6; i++) cp16(wb + (tid + i * 256) * 16, wsrc + tid + i * 256);
    }
    CP_COMMIT(); CP_WAIT(0);
    __syncthreads();

    ull acc[2][8];
    #pragma unroll
    for (int p = 0; p < 2; p++)
        #pragma unroll
        for (int j = 0; j < 8; j++) acc[p][j] = 0ULL;

    #pragma unroll 4
    for (int ci = 0; ci < 32; ci++) {
        #pragma unroll
        for (int kh = 0; kh < 3; kh++) {
            int r = 2 * ty + kh;
            ulonglong2 in2 = *(const ulonglong2*)&s_in[(ci * 9 + r) * 64 + 4 * tx];
            const float* wp = &s_w[(ci * 3 + kh) * 64 + tc * 16];
            ulonglong2 wA = *(const ulonglong2*)(wp);
            ulonglong2 wB = *(const ulonglong2*)(wp + 4);
            ulonglong2 wC = *(const ulonglong2*)(wp + 8);
            ulonglong2 wD = *(const ulonglong2*)(wp + 12);
            ffma2(acc[0][0], in2.x, wA.x); ffma2(acc[0][1], in2.x, wA.y);
            ffma2(acc[0][2], in2.x, wB.x); ffma2(acc[0][3], in2.x, wB.y);
            ffma2(acc[0][4], in2.x, wC.x); ffma2(acc[0][5], in2.x, wC.y);
            ffma2(acc[0][6], in2.x, wD.x); ffma2(acc[0][7], in2.x, wD.y);
            ffma2(acc[1][0], in2.y, wA.x); ffma2(acc[1][1], in2.y, wA.y);
            ffma2(acc[1][2], in2.y, wB.x); ffma2(acc[1][3], in2.y, wB.y);
            ffma2(acc[1][4], in2.y, wC.x); ffma2(acc[1][5], in2.y, wC.y);
            ffma2(acc[1][6], in2.y, wD.x); ffma2(acc[1][7], in2.y, wD.y);
        }
    }
    int y = y0 + ty;
    #pragma unroll
    for (int j = 0; j < 8; j++) {
        int co = tc * 8 + j;
        float4 o;
        unpack2(acc[0][j], o.x, o.y);
        unpack2(acc[1][j], o.z, o.w);
        *(float4*)&g_vraw[((size_t)(n * 32 + co) * HO + y) * WO + x0 + 4 * tx] = o;
    }
}

// ---------------- 6) horizontal CondConv (1x3, s2) — widened ----------------
#define H_ARR   4096
#define H_W_OFF 12288
#define H_SMEM_BYTES ((3*4096 + 6144) * 4)
__global__ void __launch_bounds__(128)
h_kernel(const float* __restrict__ x) {
    extern __shared__ float sm[];
    const int tid = threadIdx.x;
    const int tx = tid & 15, ty = (tid >> 4) & 1, tc = tid >> 5;
    const int x0 = blockIdx.x * 64, y0 = blockIdx.y * 2, n = blockIdx.z;
    const uint sbase = smem_u32(sm);

    for (int i = tid; i < 3072; i += 128) {
        int arr = i >> 10, j = i & 1023;
        int row = j >> 4, g = j & 15;
        int ci = row >> 1, r = row & 1;
        int gy = 2 * (y0 + r);
        const float* src = (arr == 0 ? g_ods : arr == 1 ? g_ev : g_od)
                           + ((size_t)(n * C_IN + C_H + ci) * HI + gy) * 192 + x0 + g * 4;
        cp16(sbase + (uint)i * 16, src);
    }
    {
        const float4* wsrc = (const float4*)(g_wh + (size_t)n * 32 * 192);
        uint wb = sbase + H_W_OFF * 4;
        #pragma unroll
        for (int i = 0; i < 12; i++) cp16(wb + (tid + i * 128) * 16, wsrc + tid + i * 128);
    }
    CP_COMMIT(); CP_WAIT(0);
    __syncthreads();

    const float* s_w = sm + H_W_OFF;

    ull acc[2][8];
    #pragma unroll
    for (int p = 0; p < 2; p++)
        #pragma unroll
        for (int j = 0; j < 8; j++) acc[p][j] = 0ULL;

    #pragma unroll 4
    for (int ci = 0; ci < 32; ci++) {
        const int o = (ci * 2 + ty) * 64 + 4 * tx;
        ulonglong2 pk[3] = { *(const ulonglong2*)&sm[0*H_ARR + o],
                             *(const ulonglong2*)&sm[1*H_ARR + o],
                             *(const ulonglong2*)&sm[2*H_ARR + o] };
        #pragma unroll
        for (int kw = 0; kw < 3; kw++) {
            const float* wp = &s_w[(ci * 3 + kw) * 64 + tc * 16];
            ulonglong2 wA = *(const ulonglong2*)(wp);
            ulonglong2 wB = *(const ulonglong2*)(wp + 4);
            ulonglong2 wC = *(const ulonglong2*)(wp + 8);
            ulonglong2 wD = *(const ulonglong2*)(wp + 12);
            ffma2(acc[0][0], pk[kw].x, wA.x); ffma2(acc[0][1], pk[kw].x, wA.y);
            ffma2(acc[0][2], pk[kw].x, wB.x); ffma2(acc[0][3], pk[kw].x, wB.y);
            ffma2(acc[0][4], pk[kw].x, wC.x); ffma2(acc[0][5], pk[kw].x, wC.y);
            ffma2(acc[0][6], pk[kw].x, wD.x); ffma2(acc[0][7], pk[kw].x, wD.y);
            ffma2(acc[1][0], pk[kw].y, wA.x); ffma2(acc[1][1], pk[kw].y, wA.y);
            ffma2(acc[1][2], pk[kw].y, wB.x); ffma2(acc[1][3], pk[kw].y, wB.y);
            ffma2(acc[1][4], pk[kw].y, wC.x); ffma2(acc[1][5], pk[kw].y, wC.y);
            ffma2(acc[1][6], pk[kw].y, wD.x); ffma2(acc[1][7], pk[kw].y, wD.y);
        }
    }
    int y = y0 + ty;
    #pragma unroll
    for (int j = 0; j < 8; j++) {
        int co = tc * 8 + j;
        float4 o;
        unpack2(acc[0][j], o.x, o.y);
        unpack2(acc[1][j], o.z, o.w);
        *(float4*)&g_hraw[((size_t)(n * 32 + co) * HO + y) * WO + x0 + 4 * tx] = o;
    }
}

// ---------------- 7) BN statistics ----------------
__global__ void stats_kernel() {
    int bid = blockIdx.x;
    int dir = bid >> 7, c = (bid >> 2) & 31, sl = bid & 3;
    const float* base = dir ? g_hraw : g_vraw;
    float s = 0.f, q = 0.f;
    for (int i = threadIdx.x; i < 18432; i += 256) {
        int e4 = sl * 18432 + i;
        int n = e4 / 9216, ri = e4 % 9216;
        float4 v = ((const float4*)(base + (size_t)(n * 32 + c) * HWO))[ri];
        s += v.x + v.y + v.z + v.w;
        q += v.x * v.x + v.y * v.y + v.z * v.z + v.w * v.w;
    }
    __shared__ float red[512];
    red[threadIdx.x] = s; red[256 + threadIdx.x] = q;
    __syncthreads();
    for (int o = 128; o > 0; o >>= 1) {
        if (threadIdx.x < o) {
            red[threadIdx.x] += red[threadIdx.x + o];
            red[256 + threadIdx.x] += red[256 + threadIdx.x + o];
        }
        __syncthreads();
    }
    if (threadIdx.x == 0) {
        atomicAdd(&g_stats[(dir * 32 + c) * 2],     red[0]);
        atomicAdd(&g_stats[(dir * 32 + c) * 2 + 1], red[256]);
    }
}

// ---------------- 8) BN apply + shuffle ----------------
__global__ void bn_kernel(const float* __restrict__ gv, const float* __restrict__ bv,
                          const float* __restrict__ gh, const float* __restrict__ bh,
                          float* __restrict__ out) {
    int bid = blockIdx.x;
    int dir = bid >> 8, co = (bid >> 3) & 31, n = bid & 7;
    float sum = g_stats[(dir * 32 + co) * 2];
    float sq  = g_stats[(dir * 32 + co) * 2 + 1];
    const float inv = 1.f / (float)NPIX_CH;
    float m = sum * inv;
    float var = sq * inv - m * m;
    float gam = (dir ? gh : gv)[co];
    float bet = (dir ? bh : bv)[co];
    float scale = gam * rsqrtf(var + 1e-5f);
    float shift = bet - m * scale;
    int oc = ((co & 15) << 3) + 4 + 2 * dir + (co >> 4);
    const float4* src = (const float4*)((dir ? g_hraw : g_vraw) + (size_t)(n * 32 + co) * HWO);
    float4* dst = (float4*)(out + (size_t)(n * 128 + oc) * HWO);
    for (int i = threadIdx.x; i < 9216; i += 256) {
        float4 v = src[i];
        v.x = v.x * scale + shift; v.y = v.y * scale + shift;
        v.z = v.z * scale + shift; v.w = v.w * scale + shift;
        dst[i] = v;
    }
}

// ---------------- launch ----------------
extern "C" void kernel_launch(void* const* d_in, const int* in_sizes, int n_in,
                              void* d_out, int out_size) {
    const float* x      = (const float*)d_in[0];
    const float* sq_w   = (const float*)d_in[1];
    const float* sq_b   = (const float*)d_in[2];
    const float* aw_v   = (const float*)d_in[3];
    const float* ab_v   = (const float*)d_in[4];
    const float* w_v    = (const float*)d_in[5];
    const float* bn_v_g = (const float*)d_in[6];
    const float* bn_v_b = (const float*)d_in[7];
    const float* aw_h   = (const float*)d_in[8];
    const float* ab_h   = (const float*)d_in[9];
    const float* w_h    = (const float*)d_in[10];
    const float* bn_h_g = (const float*)d_in[11];
    const float* bn_h_b = (const float*)d_in[12];
    float* out = (float*)d_out;

    static cudaStream_t s1 = nullptr;
    static cudaEvent_t e_deint = nullptr, e_join = nullptr;
    if (!s1) {
        cudaFuncSetAttribute(sq_kernel, cudaFuncAttributeMaxDynamicSharedMemorySize, SQ_SMEM_BYTES);
        cudaFuncSetAttribute(v_kernel,  cudaFuncAttributeMaxDynamicSharedMemorySize, V_SMEM_BYTES);
        cudaFuncSetAttribute(h_kernel,  cudaFuncAttributeMaxDynamicSharedMemorySize, H_SMEM_BYTES);
        cudaStreamCreateWithFlags(&s1, cudaStreamNonBlocking);
        cudaEventCreateWithFlags(&e_deint, cudaEventDisableTiming);
        cudaEventCreateWithFlags(&e_join, cudaEventDisableTiming);
    }

    // main stream (critical path): sq weight prep -> deint -> sq
    sqprep_kernel<<<144, 256>>>(sq_w);
    deint_kernel<<<N_B * C_IN, 256>>>(x);
    cudaEventRecord(e_deint, 0);

    // side stream: att -> vh weight prep -> v -> h -> stats -> bn
    cudaStreamWaitEvent(s1, e_deint, 0);
    att_kernel<<<1, 128, 0, s1>>>(aw_v, ab_v, aw_h, ab_h);
    vhprep_kernel<<<192, 256, 0, s1>>>(w_v, w_h);
    v_kernel<<<dim3(WO/64, HO/4, N_B), 256, V_SMEM_BYTES, s1>>>(x);
    h_kernel<<<dim3(WO/64, HO/2, N_B), 128, H_SMEM_BYTES, s1>>>(x);
    stats_kernel<<<256, 256, 0, s1>>>();
    bn_kernel<<<512, 256, 0, s1>>>(bn_v_g, bn_v_b, bn_h_g, bn_h_b, out);
    cudaEventRecord(e_join, s1);

    // main stream: sq conv starts immediately after deint
    sq_kernel<<<dim3(WO/64, HO/4, N_B), 256, SQ_SMEM_BYTES>>>(x, sq_b, out);

    // join
    cudaStreamWaitEvent(0, e_join, 0);
}

// round 16
// speedup vs baseline: 1.5069x; 1.5069x over previous
#include <cuda_runtime.h>
#include <math.h>

typedef unsigned long long ull;
typedef unsigned int uint;

#define N_B 8
#define C_IN 64
#define C_H 32
#define HI 384
#define WI 384
#define HO 192
#define WO 192
#define HWI (HI*WI)
#define HWO (HO*WO)
#define NPIX_CH (N_B*HWO)

// ---------------- scratch ----------------
__device__ float g_mean[N_B*C_IN];
__device__ float g_att[2*N_B*4];
__device__ float g_sqw[C_IN*9*128];                      // [ci][k9][co*2 dup]
__device__ float g_wv[N_B*C_H*3*64];
__device__ float g_wh[N_B*C_H*3*64];
__device__ float g_ev [(size_t)N_B*C_IN*HI*192];         // Ev[k]  = x[2k]
__device__ float g_od [(size_t)N_B*C_IN*HI*192];         // Od[k]  = x[2k+1]
__device__ float g_ods[(size_t)N_B*C_IN*HI*192];         // OdS[k] = x[2k-1], OdS[0]=0
__device__ float g_vraw[(size_t)N_B*C_H*HWO];
__device__ float g_hraw[(size_t)N_B*C_H*HWO];
__device__ float g_stats[2*C_H*2];

// ---------------- helpers ----------------
__device__ __forceinline__ void unpack2(ull v, float& a, float& b) {
    asm("mov.b64 {%0, %1}, %2;" : "=f"(a), "=f"(b) : "l"(v));
}
__device__ __forceinline__ void ffma2(ull& d, ull a, ull b) {
    asm("fma.rn.f32x2 %0, %1, %2, %0;" : "+l"(d) : "l"(a), "l"(b));
}
__device__ __forceinline__ uint smem_u32(const void* p) {
    uint a; asm("{ .reg .u64 t; cvta.to.shared.u64 t, %1; cvt.u32.u64 %0, t; }" : "=r"(a) : "l"(p));
    return a;
}
__device__ __forceinline__ void cp16(uint dst, const void* src) {
    asm volatile("{ .reg .u64 g; cvta.to.global.u64 g, %1;"
                 " cp.async.cg.shared.global [%0], [g], 16; }"
                 :: "r"(dst), "l"(src) : "memory");
}
__device__ __forceinline__ void cp16z(uint dst, const void* src, uint sz) {
    asm volatile("{ .reg .u64 g; cvta.to.global.u64 g, %1;"
                 " cp.async.cg.shared.global [%0], [g], 16, %2; }"
                 :: "r"(dst), "l"(src), "r"(sz) : "memory");
}
#define CP_COMMIT() asm volatile("cp.async.commit_group;" ::: "memory")
#define CP_WAIT(n)  asm volatile("cp.async.wait_group %0;" :: "n"(n) : "memory")

// ---------------- 1) global deinterleave + channel sums (R14 shuffle version) ----------------
__global__ void __launch_bounds__(256)
deint_kernel(const float* __restrict__ x) {
    int nc = blockIdx.x;
    const float* src = x + (size_t)nc * HWI;
    float* ev  = g_ev  + (size_t)nc * HI * 192;
    float* od  = g_od  + (size_t)nc * HI * 192;
    float* ods = g_ods + (size_t)nc * HI * 192;
    const int lane = threadIdx.x & 31, wid = threadIdx.x >> 5;
    float s = 0.f;

    for (int row = wid; row < HI; row += 8) {
        const float* r = src + (size_t)row * WI;
        float* evr  = ev  + row * 192;
        float* odr  = od  + row * 192;
        float* odsr = ods + row * 192;
        float carry = 0.f;
        #pragma unroll
        for (int it = 0; it < 2; it++) {
            int g = it * 32 + lane;
            bool act = g < 48;
            float4 a = act ? *(const float4*)(r + 8 * g)     : make_float4(0,0,0,0);
            float4 b = act ? *(const float4*)(r + 8 * g + 4) : make_float4(0,0,0,0);
            float myhi = b.w;
            float prev = __shfl_up_sync(0xffffffffu, myhi, 1);
            if (lane == 0) prev = carry;
            if (act) {
                *(float4*)(evr  + 4*g) = make_float4(a.x, a.z, b.x, b.z);
                *(float4*)(odr  + 4*g) = make_float4(a.y, a.w, b.y, b.w);
                *(float4*)(odsr + 4*g) = make_float4(prev, a.y, a.w, b.y);
                s += a.x + a.y + a.z + a.w + b.x + b.y + b.z + b.w;
            }
            carry = __shfl_sync(0xffffffffu, myhi, 31);
        }
    }
    __shared__ float red[256];
    red[threadIdx.x] = s; __syncthreads();
    for (int o = 128; o > 0; o >>= 1) {
        if (threadIdx.x < o) red[threadIdx.x] += red[threadIdx.x + o];
        __syncthreads();
    }
    if (threadIdx.x == 0) g_mean[nc] = red[0];
}

// ---------------- 2a) sq weight transpose (independent of x / attention) ----------------
__global__ void sqprep_kernel(const float* __restrict__ sq_w) {
    int idx = blockIdx.x * 256 + threadIdx.x;      // 144 blocks
    if (idx < C_IN*9*64) {
        int co = idx & 63, k = (idx >> 6) % 9, ci = idx / 576;
        float w = sq_w[(co * C_IN + ci) * 9 + k];
        int o = (ci * 9 + k) * 128 + co * 2;
        g_sqw[o] = w; g_sqw[o + 1] = w;
    }
}

// ---------------- 2b) attention + zero stats (side stream) ----------------
__global__ void att_kernel(const float* __restrict__ aw_v, const float* __restrict__ ab_v,
                           const float* __restrict__ aw_h, const float* __restrict__ ab_h) {
    int t = threadIdx.x;
    if (t < 64) {
        int dir = t >> 5, n = (t >> 2) & 7, k = t & 3;
        const float* aw = dir ? aw_h : aw_v;
        const float* ab = dir ? ab_h : ab_v;
        const float* m = g_mean + n * C_IN + dir * C_H;
        float s = 0.f;
        #pragma unroll
        for (int ci = 0; ci < C_H; ci++) s += m[ci] * aw[k * C_H + ci];
        s = s * (1.f / (float)HWI) + ab[k];
        g_att[t] = 1.f / (1.f + expf(-s));
    }
    if (t < 128) g_stats[t] = 0.f;
}

// ---------------- 2c) v/h expert aggregation (side stream) ----------------
__global__ void vhprep_kernel(const float* __restrict__ w_v, const float* __restrict__ w_h) {
    int r = blockIdx.x * 256 + threadIdx.x;        // 192 blocks
    if (r < 2*24576) {
        int dir = r / 24576; r %= 24576;
        int co = r & 31, kh = (r >> 5) % 3, ci = (r / 96) & 31, n = r / 3072;
        const float* w = dir ? w_h : w_v;
        const float* att = &g_att[dir * 32 + n * 4];
        float v = 0.f;
        #pragma unroll
        for (int k = 0; k < 4; k++) v += att[k] * w[((k * 32 + co) * 32 + ci) * 3 + kh];
        float* dst = dir ? g_wh : g_wv;
        int o = ((n * 32 + ci) * 3 + kh) * 64 + co * 2;
        dst[o] = v; dst[o + 1] = v;
    }
}

// ---------------- 4) square 3x3 s2 conv — big tile + row reuse ----------------
#define SQ_W_OFF   9216
#define SQ_ST      13824
#define SQ_SMEM_BYTES (2*SQ_ST*4)

__global__ void __launch_bounds__(256, 2)
sq_kernel(const float* __restrict__ x, const float* __restrict__ sq_b, float* __restrict__ out) {
    extern __shared__ float sm[];
    const int tid = threadIdx.x;
    const int tx = tid & 15, ty = (tid >> 4) & 1, tc = tid >> 5;
    const int lane = tid & 31, wid = tid >> 5;
    const int x0 = blockIdx.x * 64, y0 = blockIdx.y * 4, n = blockIdx.z;
    const int gy0 = 2*y0 - 1;
    const uint sbase = smem_u32(sm);

    ull acc[2][2][8];
    #pragma unroll
    for (int a = 0; a < 2; a++)
        #pragma unroll
        for (int b = 0; b < 2; b++)
            #pragma unroll
            for (int j = 0; j < 8; j++) acc[a][b][j] = 0ULL;

    auto load_chunk = [&](int ci0, int stage) {
        uint st = sbase + (uint)stage * (SQ_ST * 4);
        for (int row = wid; row < 36; row += 8) {
            int ci = row / 9, r = row - ci * 9;
            int gy = gy0 + r;
            bool vy = (gy >= 0);
            size_t rb = ((size_t)(n * C_IN + ci0 + ci) * HI + (vy ? gy : 0)) * 192 + x0;
            uint so = st + (uint)row * 64 * 4;
            uint sz = vy ? 16u : 0u;
            #pragma unroll
            for (int i = lane; i < 48; i += 32) {
                int arr = i >> 4, g = i & 15;
                const float* gs = (arr == 0 ? g_ods : arr == 1 ? g_ev : g_od) + rb + g * 4;
                cp16z(so + (uint)arr * (2304 * 4) + g * 16, gs, sz);
            }
        }
        const float4* wsrc = (const float4*)(g_sqw + ci0 * 9 * 128);
        uint wb = st + SQ_W_OFF * 4;
        #pragma unroll
        for (int i = 0; i < 5; i++) {
            int k = tid + i * 256;
            if (k < 1152) cp16(wb + k * 16, wsrc + k);
        }
    };

    load_chunk(0, 0);
    CP_COMMIT();

    for (int ch = 0; ch < 16; ch++) {
        if (ch < 15) {
            load_chunk((ch + 1) * 4, (ch + 1) & 1);
            CP_COMMIT();
            CP_WAIT(1);
        } else {
            CP_WAIT(0);
        }
        __syncthreads();

        const float* base = sm + (ch & 1) * SQ_ST;
        const float* sW   = base + SQ_W_OFF;

        #pragma unroll
        for (int ci = 0; ci < 4; ci++) {
            ulonglong2 row2[3];
            #pragma unroll
            for (int kh = 0; kh < 3; kh++) {
                const int oA = ((ci * 9 + 4 * ty + kh)) * 64 + 4 * tx;
                const int oB = oA + 2 * 64;
                ulonglong2 inA[3], inB[3];
                if (kh == 2) {
                    inA[0] = row2[0]; inA[1] = row2[1]; inA[2] = row2[2];
                } else {
                    inA[0] = *(const ulonglong2*)&base[0*2304 + oA];
                    inA[1] = *(const ulonglong2*)&base[1*2304 + oA];
                    inA[2] = *(const ulonglong2*)&base[2*2304 + oA];
                }
                inB[0] = *(const ulonglong2*)&base[0*2304 + oB];
                inB[1] = *(const ulonglong2*)&base[1*2304 + oB];
                inB[2] = *(const ulonglong2*)&base[2*2304 + oB];
                if (kh == 0) {
                    row2[0] = inB[0]; row2[1] = inB[1]; row2[2] = inB[2];
                }
                #pragma unroll
                for (int kw = 0; kw < 3; kw++) {
                    const float* wp = &sW[(ci * 9 + kh * 3 + kw) * 128 + tc * 16];
                    ulonglong2 wA = *(const ulonglong2*)(wp);
                    ulonglong2 wB = *(const ulonglong2*)(wp + 4);
                    ulonglong2 wC = *(const ulonglong2*)(wp + 8);
                    ulonglong2 wD = *(const ulonglong2*)(wp + 12);
                    ffma2(acc[0][0][0], inA[kw].x, wA.x); ffma2(acc[0][0][1], inA[kw].x, wA.y);
                    ffma2(acc[0][0][2], inA[kw].x, wB.x); ffma2(acc[0][0][3], inA[kw].x, wB.y);
                    ffma2(acc[0][0][4], inA[kw].x, wC.x); ffma2(acc[0][0][5], inA[kw].x, wC.y);
                    ffma2(acc[0][0][6], inA[kw].x, wD.x); ffma2(acc[0][0][7], inA[kw].x, wD.y);
                    ffma2(acc[0][1][0], inA[kw].y, wA.x); ffma2(acc[0][1][1], inA[kw].y, wA.y);
                    ffma2(acc[0][1][2], inA[kw].y, wB.x); ffma2(acc[0][1][3], inA[kw].y, wB.y);
                    ffma2(acc[0][1][4], inA[kw].y, wC.x); ffma2(acc[0][1][5], inA[kw].y, wC.y);
                    ffma2(acc[0][1][6], inA[kw].y, wD.x); ffma2(acc[0][1][7], inA[kw].y, wD.y);
                    ffma2(acc[1][0][0], inB[kw].x, wA.x); ffma2(acc[1][0][1], inB[kw].x, wA.y);
                    ffma2(acc[1][0][2], inB[kw].x, wB.x); ffma2(acc[1][0][3], inB[kw].x, wB.y);
                    ffma2(acc[1][0][4], inB[kw].x, wC.x); ffma2(acc[1][0][5], inB[kw].x, wC.y);
                    ffma2(acc[1][0][6], inB[kw].x, wD.x); ffma2(acc[1][0][7], inB[kw].x, wD.y);
                    ffma2(acc[1][1][0], inB[kw].y, wA.x); ffma2(acc[1][1][1], inB[kw].y, wA.y);
                    ffma2(acc[1][1][2], inB[kw].y, wB.x); ffma2(acc[1][1][3], inB[kw].y, wB.y);
                    ffma2(acc[1][1][4], inB[kw].y, wC.x); ffma2(acc[1][1][5], inB[kw].y, wC.y);
                    ffma2(acc[1][1][6], inB[kw].y, wD.x); ffma2(acc[1][1][7], inB[kw].y, wD.y);
                }
            }
        }
        __syncthreads();
    }

    #pragma unroll
    for (int j = 0; j < 8; j++) {
        int co = tc * 8 + j;
        float bias = sq_b[co];
        int oc = ((co & 15) << 3) + (co >> 4);
        #pragma unroll
        for (int yy = 0; yy < 2; yy++) {
            int y = y0 + 2 * ty + yy;
            float4 o;
            unpack2(acc[yy][0][j], o.x, o.y);
            unpack2(acc[yy][1][j], o.z, o.w);
            o.x += bias; o.y += bias; o.z += bias; o.w += bias;
            *(float4*)&out[((size_t)(n * 128 + oc) * HO + y) * WO + x0 + 4 * tx] = o;
        }
    }
}

// ---------------- 5) vertical CondConv (3x1, s2) — widened ----------------
#define V_W_OFF  (32*9*64)
#define V_SMEM_BYTES ((32*9*64 + 32*3*64) * 4)
__global__ void __launch_bounds__(256)
v_kernel(const float* __restrict__ x) {
    extern __shared__ float sm[];
    float* s_in = sm;
    float* s_w  = sm + V_W_OFF;
    const int tid = threadIdx.x;
    const int tx = tid & 15, ty = (tid >> 4) & 3, tc = tid >> 6;
    const int x0 = blockIdx.x * 64, y0 = blockIdx.y * 4, n = blockIdx.z;
    const int gy0 = 2*y0 - 1;
    const uint sbase = smem_u32(sm);

    for (int i = tid; i < 4608; i += 256) {
        int row = i >> 4, g = i & 15;
        int ci = row / 9, r = row - ci * 9;
        int gy = gy0 + r;
        bool vy = (gy >= 0);
        const float* gs = g_ev + ((size_t)(n * C_IN + ci) * HI + (vy ? gy : 0)) * 192 + x0 + g * 4;
        cp16z(sbase + (uint)i * 16, gs, vy ? 16u : 0u);
    }
    {
        const float4* wsrc = (const float4*)(g_wv + (size_t)n * 32 * 192);
        uint wb = sbase + V_W_OFF * 4;
        #pragma unroll
        for (int i = 0; i < 6; i++) cp16(wb + (tid + i * 256) * 16, wsrc + tid + i * 256);
    }
    CP_COMMIT(); CP_WAIT(0);
    __syncthreads();

    ull acc[2][8];
    #pragma unroll
    for (int p = 0; p < 2; p++)
        #pragma unroll
        for (int j = 0; j < 8; j++) acc[p][j] = 0ULL;

    #pragma unroll 4
    for (int ci = 0; ci < 32; ci++) {
        #pragma unroll
        for (int kh = 0; kh < 3; kh++) {
            int r = 2 * ty + kh;
            ulonglong2 in2 = *(const ulonglong2*)&s_in[(ci * 9 + r) * 64 + 4 * tx];
            const float* wp = &s_w[(ci * 3 + kh) * 64 + tc * 16];
            ulonglong2 wA = *(const ulonglong2*)(wp);
            ulonglong2 wB = *(const ulonglong2*)(wp + 4);
            ulonglong2 wC = *(const ulonglong2*)(wp + 8);
            ulonglong2 wD = *(const ulonglong2*)(wp + 12);
            ffma2(acc[0][0], in2.x, wA.x); ffma2(acc[0][1], in2.x, wA.y);
            ffma2(acc[0][2], in2.x, wB.x); ffma2(acc[0][3], in2.x, wB.y);
            ffma2(acc[0][4], in2.x, wC.x); ffma2(acc[0][5], in2.x, wC.y);
            ffma2(acc[0][6], in2.x, wD.x); ffma2(acc[0][7], in2.x, wD.y);
            ffma2(acc[1][0], in2.y, wA.x); ffma2(acc[1][1], in2.y, wA.y);
            ffma2(acc[1][2], in2.y, wB.x); ffma2(acc[1][3], in2.y, wB.y);
            ffma2(acc[1][4], in2.y, wC.x); ffma2(acc[1][5], in2.y, wC.y);
            ffma2(acc[1][6], in2.y, wD.x); ffma2(acc[1][7], in2.y, wD.y);
        }
    }
    int y = y0 + ty;
    #pragma unroll
    for (int j = 0; j < 8; j++) {
        int co = tc * 8 + j;
        float4 o;
        unpack2(acc[0][j], o.x, o.y);
        unpack2(acc[1][j], o.z, o.w);
        *(float4*)&g_vraw[((size_t)(n * 32 + co) * HO + y) * WO + x0 + 4 * tx] = o;
    }
}

// ---------------- 6) horizontal CondConv (1x3, s2) — widened ----------------
#define H_ARR   4096
#define H_W_OFF 12288
#define H_SMEM_BYTES ((3*4096 + 6144) * 4)
__global__ void __launch_bounds__(128)
h_kernel(const float* __restrict__ x) {
    extern __shared__ float sm[];
    const int tid = threadIdx.x;
    const int tx = tid & 15, ty = (tid >> 4) & 1, tc = tid >> 5;
    const int x0 = blockIdx.x * 64, y0 = blockIdx.y * 2, n = blockIdx.z;
    const uint sbase = smem_u32(sm);

    for (int i = tid; i < 3072; i += 128) {
        int arr = i >> 10, j = i & 1023;
        int row = j >> 4, g = j & 15;
        int ci = row >> 1, r = row & 1;
        int gy = 2 * (y0 + r);
        const float* src = (arr == 0 ? g_ods : arr == 1 ? g_ev : g_od)
                           + ((size_t)(n * C_IN + C_H + ci) * HI + gy) * 192 + x0 + g * 4;
        cp16(sbase + (uint)i * 16, src);
    }
    {
        const float4* wsrc = (const float4*)(g_wh + (size_t)n * 32 * 192);
        uint wb = sbase + H_W_OFF * 4;
        #pragma unroll
        for (int i = 0; i < 12; i++) cp16(wb + (tid + i * 128) * 16, wsrc + tid + i * 128);
    }
    CP_COMMIT(); CP_WAIT(0);
    __syncthreads();

    const float* s_w = sm + H_W_OFF;

    ull acc[2][8];
    #pragma unroll
    for (int p = 0; p < 2; p++)
        #pragma unroll
        for (int j = 0; j < 8; j++) acc[p][j] = 0ULL;

    #pragma unroll 4
    for (int ci = 0; ci < 32; ci++) {
        const int o = (ci * 2 + ty) * 64 + 4 * tx;
        ulonglong2 pk[3] = { *(const ulonglong2*)&sm[0*H_ARR + o],
                             *(const ulonglong2*)&sm[1*H_ARR + o],
                             *(const ulonglong2*)&sm[2*H_ARR + o] };
        #pragma unroll
        for (int kw = 0; kw < 3; kw++) {
            const float* wp = &s_w[(ci * 3 + kw) * 64 + tc * 16];
            ulonglong2 wA = *(const ulonglong2*)(wp);
            ulonglong2 wB = *(const ulonglong2*)(wp + 4);
            ulonglong2 wC = *(const ulonglong2*)(wp + 8);
            ulonglong2 wD = *(const ulonglong2*)(wp + 12);
            ffma2(acc[0][0], pk[kw].x, wA.x); ffma2(acc[0][1], pk[kw].x, wA.y);
            ffma2(acc[0][2], pk[kw].x, wB.x); ffma2(acc[0][3], pk[kw].x, wB.y);
            ffma2(acc[0][4], pk[kw].x, wC.x); ffma2(acc[0][5], pk[kw].x, wC.y);
            ffma2(acc[0][6], pk[kw].x, wD.x); ffma2(acc[0][7], pk[kw].x, wD.y);
            ffma2(acc[1][0], pk[kw].y, wA.x); ffma2(acc[1][1], pk[kw].y, wA.y);
            ffma2(acc[1][2], pk[kw].y, wB.x); ffma2(acc[1][3], pk[kw].y, wB.y);
            ffma2(acc[1][4], pk[kw].y, wC.x); ffma2(acc[1][5], pk[kw].y, wC.y);
            ffma2(acc[1][6], pk[kw].y, wD.x); ffma2(acc[1][7], pk[kw].y, wD.y);
        }
    }
    int y = y0 + ty;
    #pragma unroll
    for (int j = 0; j < 8; j++) {
        int co = tc * 8 + j;
        float4 o;
        unpack2(acc[0][j], o.x, o.y);
        unpack2(acc[1][j], o.z, o.w);
        *(float4*)&g_hraw[((size_t)(n * 32 + co) * HO + y) * WO + x0 + 4 * tx] = o;
    }
}

// ---------------- 7) BN statistics ----------------
__global__ void stats_kernel() {
    int bid = blockIdx.x;
    int dir = bid >> 7, c = (bid >> 2) & 31, sl = bid & 3;
    const float* base = dir ? g_hraw : g_vraw;
    float s = 0.f, q = 0.f;
    for (int i = threadIdx.x; i < 18432; i += 256) {
        int e4 = sl * 18432 + i;
        int n = e4 / 9216, ri = e4 % 9216;
        float4 v = ((const float4*)(base + (size_t)(n * 32 + c) * HWO))[ri];
        s += v.x + v.y + v.z + v.w;
        q += v.x * v.x + v.y * v.y + v.z * v.z + v.w * v.w;
    }
    __shared__ float red[512];
    red[threadIdx.x] = s; red[256 + threadIdx.x] = q;
    __syncthreads();
    for (int o = 128; o > 0; o >>= 1) {
        if (threadIdx.x < o) {
            red[threadIdx.x] += red[threadIdx.x + o];
            red[256 + threadIdx.x] += red[256 + threadIdx.x + o];
        }
        __syncthreads();
    }
    if (threadIdx.x == 0) {
        atomicAdd(&g_stats[(dir * 32 + c) * 2],     red[0]);
        atomicAdd(&g_stats[(dir * 32 + c) * 2 + 1], red[256]);
    }
}

// ---------------- 8) BN apply + shuffle ----------------
__global__ void bn_kernel(const float* __restrict__ gv, const float* __restrict__ bv,
                          const float* __restrict__ gh, const float* __restrict__ bh,
                          float* __restrict__ out) {
    int bid = blockIdx.x;
    int dir = bid >> 8, co = (bid >> 3) & 31, n = bid & 7;
    float sum = g_stats[(dir * 32 + co) * 2];
    float sq  = g_stats[(dir * 32 + co) * 2 + 1];
    const float inv = 1.f / (float)NPIX_CH;
    float m = sum * inv;
    float var = sq * inv - m * m;
    float gam = (dir ? gh : gv)[co];
    float bet = (dir ? bh : bv)[co];
    float scale = gam * rsqrtf(var + 1e-5f);
    float shift = bet - m * scale;
    int oc = ((co & 15) << 3) + 4 + 2 * dir + (co >> 4);
    const float4* src = (const float4*)((dir ? g_hraw : g_vraw) + (size_t)(n * 32 + co) * HWO);
    float4* dst = (float4*)(out + (size_t)(n * 128 + oc) * HWO);
    for (int i = threadIdx.x; i < 9216; i += 256) {
        float4 v = src[i];
        v.x = v.x * scale + shift; v.y = v.y * scale + shift;
        v.z = v.z * scale + shift; v.w = v.w * scale + shift;
        dst[i] = v;
    }
}

// ---------------- launch ----------------
extern "C" void kernel_launch(void* const* d_in, const int* in_sizes, int n_in,
                              void* d_out, int out_size) {
    const float* x      = (const float*)d_in[0];
    const float* sq_w   = (const float*)d_in[1];
    const float* sq_b   = (const float*)d_in[2];
    const float* aw_v   = (const float*)d_in[3];
    const float* ab_v   = (const float*)d_in[4];
    const float* w_v    = (const float*)d_in[5];
    const float* bn_v_g = (const float*)d_in[6];
    const float* bn_v_b = (const float*)d_in[7];
    const float* aw_h   = (const float*)d_in[8];
    const float* ab_h   = (const float*)d_in[9];
    const float* w_h    = (const float*)d_in[10];
    const float* bn_h_g = (const float*)d_in[11];
    const float* bn_h_b = (const float*)d_in[12];
    float* out = (float*)d_out;

    static cudaStream_t s1 = nullptr;
    static cudaEvent_t e_deint = nullptr, e_join = nullptr;
    if (!s1) {
        cudaFuncSetAttribute(sq_kernel, cudaFuncAttributeMaxDynamicSharedMemorySize, SQ_SMEM_BYTES);
        cudaFuncSetAttribute(v_kernel,  cudaFuncAttributeMaxDynamicSharedMemorySize, V_SMEM_BYTES);
        cudaFuncSetAttribute(h_kernel,  cudaFuncAttributeMaxDynamicSharedMemorySize, H_SMEM_BYTES);
        cudaStreamCreateWithFlags(&s1, cudaStreamNonBlocking);
        cudaEventCreateWithFlags(&e_deint, cudaEventDisableTiming);
        cudaEventCreateWithFlags(&e_join, cudaEventDisableTiming);
    }

    // main stream (critical path): sq weight prep -> deint
    sqprep_kernel<<<144, 256>>>(sq_w);
    deint_kernel<<<N_B * C_IN, 256>>>(x);
    cudaEventRecord(e_deint, 0);

    // side stream: att -> vh weight prep -> v -> h -> stats -> bn
    cudaStreamWaitEvent(s1, e_deint, 0);
    att_kernel<<<1, 128, 0, s1>>>(aw_v, ab_v, aw_h, ab_h);
    vhprep_kernel<<<192, 256, 0, s1>>>(w_v, w_h);
    v_kernel<<<dim3(WO/64, HO/4, N_B), 256, V_SMEM_BYTES, s1>>>(x);
    h_kernel<<<dim3(WO/64, HO/2, N_B), 128, H_SMEM_BYTES, s1>>>(x);
    stats_kernel<<<256, 256, 0, s1>>>();
    bn_kernel<<<512, 256, 0, s1>>>(bn_v_g, bn_v_b, bn_h_g, bn_h_b, out);
    cudaEventRecord(e_join, s1);

    // main stream: sq conv starts immediately after deint
    sq_kernel<<<dim3(WO/64, HO/4, N_B), 256, SQ_SMEM_BYTES>>>(x, sq_b, out);

    // join
    cudaStreamWaitEvent(0, e_join, 0);
}

// round 17
// speedup vs baseline: 1.5529x; 1.0305x over previous
#include <cuda_runtime.h>
#include <math.h>

typedef unsigned long long ull;
typedef unsigned int uint;

#define N_B 8
#define C_IN 64
#define C_H 32
#define HI 384
#define WI 384
#define HO 192
#define WO 192
#define HWI (HI*WI)
#define HWO (HO*WO)
#define NPIX_CH (N_B*HWO)

// ---------------- scratch ----------------
__device__ float g_mean[N_B*C_IN];
__device__ float g_att[2*N_B*4];
__device__ float g_sqw[C_IN*9*128];                      // [ci][k9][co*2 dup]
__device__ float g_wv[N_B*C_H*3*64];
__device__ float g_wh[N_B*C_H*3*64];
__device__ float g_ev [(size_t)N_B*C_IN*HI*192];         // Ev[k]  = x[2k],   pitch 192
__device__ float g_odp[(size_t)N_B*C_IN*HI*208];         // OdP: [0..15]=0 pad, [16+k]=x[2k+1], pitch 208
__device__ float g_vraw[(size_t)N_B*C_H*HWO];
__device__ float g_hraw[(size_t)N_B*C_H*HWO];
__device__ float g_stats[2*C_H*2];

// ---------------- helpers ----------------
__device__ __forceinline__ void unpack2(ull v, float& a, float& b) {
    asm("mov.b64 {%0, %1}, %2;" : "=f"(a), "=f"(b) : "l"(v));
}
__device__ __forceinline__ void ffma2(ull& d, ull a, ull b) {
    asm("fma.rn.f32x2 %0, %1, %2, %0;" : "+l"(d) : "l"(a), "l"(b));
}
__device__ __forceinline__ uint smem_u32(const void* p) {
    uint a; asm("{ .reg .u64 t; cvta.to.shared.u64 t, %1; cvt.u32.u64 %0, t; }" : "=r"(a) : "l"(p));
    return a;
}
__device__ __forceinline__ void cp16(uint dst, const void* src) {
    asm volatile("{ .reg .u64 g; cvta.to.global.u64 g, %1;"
                 " cp.async.cg.shared.global [%0], [g], 16; }"
                 :: "r"(dst), "l"(src) : "memory");
}
__device__ __forceinline__ void cp16z(uint dst, const void* src, uint sz) {
    asm volatile("{ .reg .u64 g; cvta.to.global.u64 g, %1;"
                 " cp.async.cg.shared.global [%0], [g], 16, %2; }"
                 :: "r"(dst), "l"(src), "r"(sz) : "memory");
}
__device__ __forceinline__ void cp4z(uint dst, const float* src, uint sz) {
    asm volatile("{ .reg .u64 g; cvta.to.global.u64 g, %1;"
                 " cp.async.ca.shared.global [%0], [g], 4, %2; }"
                 :: "r"(dst), "l"(src), "r"(sz) : "memory");
}
#define CP_COMMIT() asm volatile("cp.async.commit_group;" ::: "memory")
#define CP_WAIT(n)  asm volatile("cp.async.wait_group %0;" :: "n"(n) : "memory")

// ---------------- 1) global deinterleave (2 arrays) + channel sums ----------------
__global__ void __launch_bounds__(256)
deint_kernel(const float* __restrict__ x) {
    int nc = blockIdx.x;
    const float* src = x + (size_t)nc * HWI;
    float* ev  = g_ev  + (size_t)nc * HI * 192;
    float* odp = g_odp + (size_t)nc * HI * 208;
    const int lane = threadIdx.x & 31, wid = threadIdx.x >> 5;
    float s = 0.f;

    for (int row = wid; row < HI; row += 8) {
        const float* r = src + (size_t)row * WI;
        float* evr  = ev  + row * 192;
        float* odpr = odp + row * 208;
        if (lane < 4) *(float4*)(odpr + 4 * lane) = make_float4(0.f, 0.f, 0.f, 0.f);
        #pragma unroll
        for (int it = 0; it < 2; it++) {
            int g = it * 32 + lane;
            if (g < 48) {
                float4 a = *(const float4*)(r + 8 * g);
                float4 b = *(const float4*)(r + 8 * g + 4);
                *(float4*)(evr  + 4*g)      = make_float4(a.x, a.z, b.x, b.z);
                *(float4*)(odpr + 16 + 4*g) = make_float4(a.y, a.w, b.y, b.w);
                s += a.x + a.y + a.z + a.w + b.x + b.y + b.z + b.w;
            }
        }
    }
    __shared__ float red[256];
    red[threadIdx.x] = s; __syncthreads();
    for (int o = 128; o > 0; o >>= 1) {
        if (threadIdx.x < o) red[threadIdx.x] += red[threadIdx.x + o];
        __syncthreads();
    }
    if (threadIdx.x == 0) g_mean[nc] = red[0];
}

// ---------------- 2a) sq weight transpose ----------------
__global__ void sqprep_kernel(const float* __restrict__ sq_w) {
    int idx = blockIdx.x * 256 + threadIdx.x;      // 144 blocks
    if (idx < C_IN*9*64) {
        int co = idx & 63, k = (idx >> 6) % 9, ci = idx / 576;
        float w = sq_w[(co * C_IN + ci) * 9 + k];
        int o = (ci * 9 + k) * 128 + co * 2;
        g_sqw[o] = w; g_sqw[o + 1] = w;
    }
}

// ---------------- 2b) attention + zero stats ----------------
__global__ void att_kernel(const float* __restrict__ aw_v, const float* __restrict__ ab_v,
                           const float* __restrict__ aw_h, const float* __restrict__ ab_h) {
    int t = threadIdx.x;
    if (t < 64) {
        int dir = t >> 5, n = (t >> 2) & 7, k = t & 3;
        const float* aw = dir ? aw_h : aw_v;
        const float* ab = dir ? ab_h : ab_v;
        const float* m = g_mean + n * C_IN + dir * C_H;
        float s = 0.f;
        #pragma unroll
        for (int ci = 0; ci < C_H; ci++) s += m[ci] * aw[k * C_H + ci];
        s = s * (1.f / (float)HWI) + ab[k];
        g_att[t] = 1.f / (1.f + expf(-s));
    }
    if (t < 128) g_stats[t] = 0.f;
}

// ---------------- 2c) v/h expert aggregation ----------------
__global__ void vhprep_kernel(const float* __restrict__ w_v, const float* __restrict__ w_h) {
    int r = blockIdx.x * 256 + threadIdx.x;        // 192 blocks
    if (r < 2*24576) {
        int dir = r / 24576; r %= 24576;
        int co = r & 31, kh = (r >> 5) % 3, ci = (r / 96) & 31, n = r / 3072;
        const float* w = dir ? w_h : w_v;
        const float* att = &g_att[dir * 32 + n * 4];
        float v = 0.f;
        #pragma unroll
        for (int k = 0; k < 4; k++) v += att[k] * w[((k * 32 + co) * 32 + ci) * 3 + kh];
        float* dst = dir ? g_wh : g_wv;
        int o = ((n * 32 + ci) * 3 + kh) * 64 + co * 2;
        dst[o] = v; dst[o + 1] = v;
    }
}

// ---------------- 4) square 3x3 s2 conv — big tile + row reuse ----------------
// smem arrays per stage (floats): arr0=OdS[36*64] arr1=Ev[36*64] arr2=Od[36*64] W[4608]
#define SQ_W_OFF   9216
#define SQ_ST      13824
#define SQ_SMEM_BYTES (2*SQ_ST*4)

__global__ void __launch_bounds__(256, 2)
sq_kernel(const float* __restrict__ x, const float* __restrict__ sq_b, float* __restrict__ out) {
    extern __shared__ float sm[];
    const int tid = threadIdx.x;
    const int tx = tid & 15, ty = (tid >> 4) & 1, tc = tid >> 5;
    const int lane = tid & 31, wid = tid >> 5;
    const int x0 = blockIdx.x * 64, y0 = blockIdx.y * 4, n = blockIdx.z;
    const int gy0 = 2*y0 - 1;
    const uint sbase = smem_u32(sm);

    ull acc[2][2][8];
    #pragma unroll
    for (int a = 0; a < 2; a++)
        #pragma unroll
        for (int b = 0; b < 2; b++)
            #pragma unroll
            for (int j = 0; j < 8; j++) acc[a][b][j] = 0ULL;

    auto load_chunk = [&](int ci0, int stage) {
        uint st = sbase + (uint)stage * (SQ_ST * 4);
        for (int row = wid; row < 36; row += 8) {
            int ci = row / 9, rr = row - ci * 9;
            int gy = gy0 + rr;
            bool vy = (gy >= 0);
            size_t chb = (size_t)(n * C_IN + ci0 + ci) * HI + (vy ? gy : 0);
            const float* evs = g_ev  + chb * 192 + x0;
            const float* odq = g_odp + chb * 208 + 16 + x0;   // Od slice
            uint so = st + (uint)row * 64 * 4;
            uint sz16 = vy ? 16u : 0u, sz4 = vy ? 4u : 0u;
            // Ev (arr1) + Od (arr2): 16 cp16 each
            if (lane < 16) cp16z(so + (uint)(1 * 2304 * 4) + lane * 16, evs + lane * 4, sz16);
            else           cp16z(so + (uint)(2 * 2304 * 4) + (lane - 16) * 16, odq + (lane - 16) * 4, sz16);
            // OdS (arr0): 64 coalesced scalar cp (pad absorbs left halo)
            cp4z(so + (uint)lane * 4,        odq - 1 + lane,      sz4);
            cp4z(so + (uint)(lane + 32) * 4, odq - 1 + lane + 32, sz4);
        }
        const float4* wsrc = (const float4*)(g_sqw + ci0 * 9 * 128);
        uint wb = st + SQ_W_OFF * 4;
        #pragma unroll
        for (int i = 0; i < 5; i++) {
            int k = tid + i * 256;
            if (k < 1152) cp16(wb + k * 16, wsrc + k);
        }
    };

    load_chunk(0, 0);
    CP_COMMIT();

    for (int ch = 0; ch < 16; ch++) {
        if (ch < 15) {
            load_chunk((ch + 1) * 4, (ch + 1) & 1);
            CP_COMMIT();
            CP_WAIT(1);
        } else {
            CP_WAIT(0);
        }
        __syncthreads();

        const float* base = sm + (ch & 1) * SQ_ST;
        const float* sW   = base + SQ_W_OFF;

        #pragma unroll
        for (int ci = 0; ci < 4; ci++) {
            ulonglong2 row2[3];
            #pragma unroll
            for (int kh = 0; kh < 3; kh++) {
                const int oA = ((ci * 9 + 4 * ty + kh)) * 64 + 4 * tx;
                const int oB = oA + 2 * 64;
                ulonglong2 inA[3], inB[3];
                if (kh == 2) {
                    inA[0] = row2[0]; inA[1] = row2[1]; inA[2] = row2[2];
                } else {
                    inA[0] = *(const ulonglong2*)&base[0*2304 + oA];
                    inA[1] = *(const ulonglong2*)&base[1*2304 + oA];
                    inA[2] = *(const ulonglong2*)&base[2*2304 + oA];
                }
                inB[0] = *(const ulonglong2*)&base[0*2304 + oB];
                inB[1] = *(const ulonglong2*)&base[1*2304 + oB];
                inB[2] = *(const ulonglong2*)&base[2*2304 + oB];
                if (kh == 0) {
                    row2[0] = inB[0]; row2[1] = inB[1]; row2[2] = inB[2];
                }
                #pragma unroll
                for (int kw = 0; kw < 3; kw++) {
                    const float* wp = &sW[(ci * 9 + kh * 3 + kw) * 128 + tc * 16];
                    ulonglong2 wA = *(const ulonglong2*)(wp);
                    ulonglong2 wB = *(const ulonglong2*)(wp + 4);
                    ulonglong2 wC = *(const ulonglong2*)(wp + 8);
                    ulonglong2 wD = *(const ulonglong2*)(wp + 12);
                    ffma2(acc[0][0][0], inA[kw].x, wA.x); ffma2(acc[0][0][1], inA[kw].x, wA.y);
                    ffma2(acc[0][0][2], inA[kw].x, wB.x); ffma2(acc[0][0][3], inA[kw].x, wB.y);
                    ffma2(acc[0][0][4], inA[kw].x, wC.x); ffma2(acc[0][0][5], inA[kw].x, wC.y);
                    ffma2(acc[0][0][6], inA[kw].x, wD.x); ffma2(acc[0][0][7], inA[kw].x, wD.y);
                    ffma2(acc[0][1][0], inA[kw].y, wA.x); ffma2(acc[0][1][1], inA[kw].y, wA.y);
                    ffma2(acc[0][1][2], inA[kw].y, wB.x); ffma2(acc[0][1][3], inA[kw].y, wB.y);
                    ffma2(acc[0][1][4], inA[kw].y, wC.x); ffma2(acc[0][1][5], inA[kw].y, wC.y);
                    ffma2(acc[0][1][6], inA[kw].y, wD.x); ffma2(acc[0][1][7], inA[kw].y, wD.y);
                    ffma2(acc[1][0][0], inB[kw].x, wA.x); ffma2(acc[1][0][1], inB[kw].x, wA.y);
                    ffma2(acc[1][0][2], inB[kw].x, wB.x); ffma2(acc[1][0][3], inB[kw].x, wB.y);
                    ffma2(acc[1][0][4], inB[kw].x, wC.x); ffma2(acc[1][0][5], inB[kw].x, wC.y);
                    ffma2(acc[1][0][6], inB[kw].x, wD.x); ffma2(acc[1][0][7], inB[kw].x, wD.y);
                    ffma2(acc[1][1][0], inB[kw].y, wA.x); ffma2(acc[1][1][1], inB[kw].y, wA.y);
                    ffma2(acc[1][1][2], inB[kw].y, wB.x); ffma2(acc[1][1][3], inB[kw].y, wB.y);
                    ffma2(acc[1][1][4], inB[kw].y, wC.x); ffma2(acc[1][1][5], inB[kw].y, wC.y);
                    ffma2(acc[1][1][6], inB[kw].y, wD.x); ffma2(acc[1][1][7], inB[kw].y, wD.y);
                }
            }
        }
        __syncthreads();
    }

    #pragma unroll
    for (int j = 0; j < 8; j++) {
        int co = tc * 8 + j;
        float bias = sq_b[co];
        int oc = ((co & 15) << 3) + (co >> 4);
        #pragma unroll
        for (int yy = 0; yy < 2; yy++) {
            int y = y0 + 2 * ty + yy;
            float4 o;
            unpack2(acc[yy][0][j], o.x, o.y);
            unpack2(acc[yy][1][j], o.z, o.w);
            o.x += bias; o.y += bias; o.z += bias; o.w += bias;
            *(float4*)&out[((size_t)(n * 128 + oc) * HO + y) * WO + x0 + 4 * tx] = o;
        }
    }
}

// ---------------- 5) vertical CondConv (3x1, s2) — widened (Ev only) ----------------
#define V_W_OFF  (32*9*64)
#define V_SMEM_BYTES ((32*9*64 + 32*3*64) * 4)
__global__ void __launch_bounds__(256)
v_kernel(const float* __restrict__ x) {
    extern __shared__ float sm[];
    float* s_in = sm;
    float* s_w  = sm + V_W_OFF;
    const int tid = threadIdx.x;
    const int tx = tid & 15, ty = (tid >> 4) & 3, tc = tid >> 6;
    const int x0 = blockIdx.x * 64, y0 = blockIdx.y * 4, n = blockIdx.z;
    const int gy0 = 2*y0 - 1;
    const uint sbase = smem_u32(sm);

    for (int i = tid; i < 4608; i += 256) {
        int row = i >> 4, g = i & 15;
        int ci = row / 9, r = row - ci * 9;
        int gy = gy0 + r;
        bool vy = (gy >= 0);
        const float* gs = g_ev + ((size_t)(n * C_IN + ci) * HI + (vy ? gy : 0)) * 192 + x0 + g * 4;
        cp16z(sbase + (uint)i * 16, gs, vy ? 16u : 0u);
    }
    {
        const float4* wsrc = (const float4*)(g_wv + (size_t)n * 32 * 192);
        uint wb = sbase + V_W_OFF * 4;
        #pragma unroll
        for (int i = 0; i < 6; i++) cp16(wb + (tid + i * 256) * 16, wsrc + tid + i * 256);
    }
    CP_COMMIT(); CP_WAIT(0);
    __syncthreads();

    ull acc[2][8];
    #pragma unroll
    for (int p = 0; p < 2; p++)
        #pragma unroll
        for (int j = 0; j < 8; j++) acc[p][j] = 0ULL;

    #pragma unroll 4
    for (int ci = 0; ci < 32; ci++) {
        #pragma unroll
        for (int kh = 0; kh < 3; kh++) {
            int r = 2 * ty + kh;
            ulonglong2 in2 = *(const ulonglong2*)&s_in[(ci * 9 + r) * 64 + 4 * tx];
            const float* wp = &s_w[(ci * 3 + kh) * 64 + tc * 16];
            ulonglong2 wA = *(const ulonglong2*)(wp);
            ulonglong2 wB = *(const ulonglong2*)(wp + 4);
            ulonglong2 wC = *(const ulonglong2*)(wp + 8);
            ulonglong2 wD = *(const ulonglong2*)(wp + 12);
            ffma2(acc[0][0], in2.x, wA.x); ffma2(acc[0][1], in2.x, wA.y);
            ffma2(acc[0][2], in2.x, wB.x); ffma2(acc[0][3], in2.x, wB.y);
            ffma2(acc[0][4], in2.x, wC.x); ffma2(acc[0][5], in2.x, wC.y);
            ffma2(acc[0][6], in2.x, wD.x); ffma2(acc[0][7], in2.x, wD.y);
            ffma2(acc[1][0], in2.y, wA.x); ffma2(acc[1][1], in2.y, wA.y);
            ffma2(acc[1][2], in2.y, wB.x); ffma2(acc[1][3], in2.y, wB.y);
            ffma2(acc[1][4], in2.y, wC.x); ffma2(acc[1][5], in2.y, wC.y);
            ffma2(acc[1][6], in2.y, wD.x); ffma2(acc[1][7], in2.y, wD.y);
        }
    }
    int y = y0 + ty;
    #pragma unroll
    for (int j = 0; j < 8; j++) {
        int co = tc * 8 + j;
        float4 o;
        unpack2(acc[0][j], o.x, o.y);
        unpack2(acc[1][j], o.z, o.w);
        *(float4*)&g_vraw[((size_t)(n * 32 + co) * HO + y) * WO + x0 + 4 * tx] = o;
    }
}

// ---------------- 6) horizontal CondConv (1x3, s2) — widened, OdP-based ----------------
#define H_ARR   4096           // 64 rows * 64 floats per array
#define H_W_OFF 12288
#define H_SMEM_BYTES ((3*4096 + 6144) * 4)
__global__ void __launch_bounds__(128)
h_kernel(const float* __restrict__ x) {
    extern __shared__ float sm[];
    const int tid = threadIdx.x;
    const int tx = tid & 15, ty = (tid >> 4) & 1, tc = tid >> 5;
    const int x0 = blockIdx.x * 64, y0 = blockIdx.y * 2, n = blockIdx.z;
    const uint sbase = smem_u32(sm);

    // Ev (arr1) + Od (arr2): 2048 cp16
    for (int i = tid; i < 2048; i += 128) {
        int arr = i >> 10, j = i & 1023;
        int row = j >> 4, g = j & 15;
        int ci = row >> 1, r = row & 1;
        int gy = 2 * (y0 + r);
        size_t chb = (size_t)(n * C_IN + C_H + ci) * HI + gy;
        const float* src = (arr == 0) ? g_ev  + chb * 192 + x0 + g * 4
                                      : g_odp + chb * 208 + 16 + x0 + g * 4;
        cp16(sbase + (uint)((1 + arr) * H_ARR + row * 64 + g * 4) * 4, src);
    }
    // OdS (arr0): 4096 coalesced scalar cp
    for (int i = tid; i < 4096; i += 128) {
        int row = i >> 6, k = i & 63;
        int ci = row >> 1, r = row & 1;
        int gy = 2 * (y0 + r);
        size_t chb = (size_t)(n * C_IN + C_H + ci) * HI + gy;
        cp4z(sbase + (uint)(row * 64 + k) * 4, g_odp + chb * 208 + 15 + x0 + k, 4u);
    }
    {
        const float4* wsrc = (const float4*)(g_wh + (size_t)n * 32 * 192);
        uint wb = sbase + H_W_OFF * 4;
        #pragma unroll
        for (int i = 0; i < 12; i++) cp16(wb + (tid + i * 128) * 16, wsrc + tid + i * 128);
    }
    CP_COMMIT(); CP_WAIT(0);
    __syncthreads();

    const float* s_w = sm + H_W_OFF;

    ull acc[2][8];
    #pragma unroll
    for (int p = 0; p < 2; p++)
        #pragma unroll
        for (int j = 0; j < 8; j++) acc[p][j] = 0ULL;

    #pragma unroll 4
    for (int ci = 0; ci < 32; ci++) {
        const int o = (ci * 2 + ty) * 64 + 4 * tx;
        ulonglong2 pk[3] = { *(const ulonglong2*)&sm[0*H_ARR + o],
                             *(const ulonglong2*)&sm[1*H_ARR + o],
                             *(const ulonglong2*)&sm[2*H_ARR + o] };
        #pragma unroll
        for (int kw = 0; kw < 3; kw++) {
            const float* wp = &s_w[(ci * 3 + kw) * 64 + tc * 16];
            ulonglong2 wA = *(const ulonglong2*)(wp);
            ulonglong2 wB = *(const ulonglong2*)(wp + 4);
            ulonglong2 wC = *(const ulonglong2*)(wp + 8);
            ulonglong2 wD = *(const ulonglong2*)(wp + 12);
            ffma2(acc[0][0], pk[kw].x, wA.x); ffma2(acc[0][1], pk[kw].x, wA.y);
            ffma2(acc[0][2], pk[kw].x, wB.x); ffma2(acc[0][3], pk[kw].x, wB.y);
            ffma2(acc[0][4], pk[kw].x, wC.x); ffma2(acc[0][5], pk[kw].x, wC.y);
            ffma2(acc[0][6], pk[kw].x, wD.x); ffma2(acc[0][7], pk[kw].x, wD.y);
            ffma2(acc[1][0], pk[kw].y, wA.x); ffma2(acc[1][1], pk[kw].y, wA.y);
            ffma2(acc[1][2], pk[kw].y, wB.x); ffma2(acc[1][3], pk[kw].y, wB.y);
            ffma2(acc[1][4], pk[kw].y, wC.x); ffma2(acc[1][5], pk[kw].y, wC.y);
            ffma2(acc[1][6], pk[kw].y, wD.x); ffma2(acc[1][7], pk[kw].y, wD.y);
        }
    }
    int y = y0 + ty;
    #pragma unroll
    for (int j = 0; j < 8; j++) {
        int co = tc * 8 + j;
        float4 o;
        unpack2(acc[0][j], o.x, o.y);
        unpack2(acc[1][j], o.z, o.w);
        *(float4*)&g_hraw[((size_t)(n * 32 + co) * HO + y) * WO + x0 + 4 * tx] = o;
    }
}

// ---------------- 7) BN statistics ----------------
__global__ void stats_kernel() {
    int bid = blockIdx.x;
    int dir = bid >> 7, c = (bid >> 2) & 31, sl = bid & 3;
    const float* base = dir ? g_hraw : g_vraw;
    float s = 0.f, q = 0.f;
    for (int i = threadIdx.x; i < 18432; i += 256) {
        int e4 = sl * 18432 + i;
        int n = e4 / 9216, ri = e4 % 9216;
        float4 v = ((const float4*)(base + (size_t)(n * 32 + c) * HWO))[ri];
        s += v.x + v.y + v.z + v.w;
        q += v.x * v.x + v.y * v.y + v.z * v.z + v.w * v.w;
    }
    __shared__ float red[512];
    red[threadIdx.x] = s; red[256 + threadIdx.x] = q;
    __syncthreads();
    for (int o = 128; o > 0; o >>= 1) {
        if (threadIdx.x < o) {
            red[threadIdx.x] += red[threadIdx.x + o];
            red[256 + threadIdx.x] += red[256 + threadIdx.x + o];
        }
        __syncthreads();
    }
    if (threadIdx.x == 0) {
        atomicAdd(&g_stats[(dir * 32 + c) * 2],     red[0]);
        atomicAdd(&g_stats[(dir * 32 + c) * 2 + 1], red[256]);
    }
}

// ---------------- 8) BN apply + shuffle ----------------
__global__ void bn_kernel(const float* __restrict__ gv, const float* __restrict__ bv,
                          const float* __restrict__ gh, const float* __restrict__ bh,
                          float* __restrict__ out) {
    int bid = blockIdx.x;
    int dir = bid >> 8, co = (bid >> 3) & 31, n = bid & 7;
    float sum = g_stats[(dir * 32 + co) * 2];
    float sq  = g_stats[(dir * 32 + co) * 2 + 1];
    const float inv = 1.f / (float)NPIX_CH;
    float m = sum * inv;
    float var = sq * inv - m * m;
    float gam = (dir ? gh : gv)[co];
    float bet = (dir ? bh : bv)[co];
    float scale = gam * rsqrtf(var + 1e-5f);
    float shift = bet - m * scale;
    int oc = ((co & 15) << 3) + 4 + 2 * dir + (co >> 4);
    const float4* src = (const float4*)((dir ? g_hraw : g_vraw) + (size_t)(n * 32 + co) * HWO);
    float4* dst = (float4*)(out + (size_t)(n * 128 + oc) * HWO);
    for (int i = threadIdx.x; i < 9216; i += 256) {
        float4 v = src[i];
        v.x = v.x * scale + shift; v.y = v.y * scale + shift;
        v.z = v.z * scale + shift; v.w = v.w * scale + shift;
        dst[i] = v;
    }
}

// ---------------- launch ----------------
extern "C" void kernel_launch(void* const* d_in, const int* in_sizes, int n_in,
                              void* d_out, int out_size) {
    const float* x      = (const float*)d_in[0];
    const float* sq_w   = (const float*)d_in[1];
    const float* sq_b   = (const float*)d_in[2];
    const float* aw_v   = (const float*)d_in[3];
    const float* ab_v   = (const float*)d_in[4];
    const float* w_v    = (const float*)d_in[5];
    const float* bn_v_g = (const float*)d_in[6];
    const float* bn_v_b = (const float*)d_in[7];
    const float* aw_h   = (const float*)d_in[8];
    const float* ab_h   = (const float*)d_in[9];
    const float* w_h    = (const float*)d_in[10];
    const float* bn_h_g = (const float*)d_in[11];
    const float* bn_h_b = (const float*)d_in[12];
    float* out = (float*)d_out;

    static cudaStream_t s1 = nullptr;
    static cudaEvent_t e_deint = nullptr, e_join = nullptr;
    if (!s1) {
        cudaFuncSetAttribute(sq_kernel, cudaFuncAttributeMaxDynamicSharedMemorySize, SQ_SMEM_BYTES);
        cudaFuncSetAttribute(v_kernel,  cudaFuncAttributeMaxDynamicSharedMemorySize, V_SMEM_BYTES);
        cudaFuncSetAttribute(h_kernel,  cudaFuncAttributeMaxDynamicSharedMemorySize, H_SMEM_BYTES);
        cudaStreamCreateWithFlags(&s1, cudaStreamNonBlocking);
        cudaEventCreateWithFlags(&e_deint, cudaEventDisableTiming);
        cudaEventCreateWithFlags(&e_join, cudaEventDisableTiming);
    }

    // main stream (critical path): sq weight prep -> deint
    sqprep_kernel<<<144, 256>>>(sq_w);
    deint_kernel<<<N_B * C_IN, 256>>>(x);
    cudaEventRecord(e_deint, 0);

    // side stream: att -> vh weight prep -> v -> h -> stats -> bn
    cudaStreamWaitEvent(s1, e_deint, 0);
    att_kernel<<<1, 128, 0, s1>>>(aw_v, ab_v, aw_h, ab_h);
    vhprep_kernel<<<192, 256, 0, s1>>>(w_v, w_h);
    v_kernel<<<dim3(WO/64, HO/4, N_B), 256, V_SMEM_BYTES, s1>>>(x);
    h_kernel<<<dim3(WO/64, HO/2, N_B), 128, H_SMEM_BYTES, s1>>>(x);
    stats_kernel<<<256, 256, 0, s1>>>();
    bn_kernel<<<512, 256, 0, s1>>>(bn_v_g, bn_v_b, bn_h_g, bn_h_b, out);
    cudaEventRecord(e_join, s1);

    // main stream: sq conv starts immediately after deint
    sq_kernel<<<dim3(WO/64, HO/4, N_B), 256, SQ_SMEM_BYTES>>>(x, sq_b, out);

    // join
    cudaStreamWaitEvent(0, e_join, 0);
}